// round 13
// baseline (speedup 1.0000x reference)
#include <cuda_runtime.h>
#include <cstdint>
#include <math.h>

constexpr int IMH = 256, IMW = 256;
constexpr int HWSZ = IMH * IMW;       // 65536
constexpr int BB = 2;

// ---------------- scratch (device globals; no runtime allocation) ----------------
__device__ float g_qkin  [(size_t)BB * 100 * HWSZ];
__device__ float g_qureys[(size_t)BB *  96 * HWSZ];
__device__ float g_value [(size_t)BB *  96 * HWSZ];
__device__ float g_val   [(size_t)BB *  96 * HWSZ];
__device__ float g_off   [(size_t)BB *  96 * HWSZ];
__device__ float g_aw    [(size_t)BB *  48 * HWSZ];
__device__ float g_attn  [(size_t)BB *  32 * HWSZ];
__device__ float g_out1  [(size_t)BB *  32 * HWSZ];
__device__ float g_out2  [(size_t)BB *  32 * HWSZ];
__device__ float g_ff1   [(size_t)BB *  32 * HWSZ];
__device__ float g_out3  [(size_t)BB *  32 * HWSZ];

__device__ __forceinline__ float lrelu(float v) { return v >= 0.f ? v : 0.1f * v; }

// ---------------- packed f32x2 helpers (Blackwell FFMA2) ----------------
__device__ __forceinline__ void ffma2(unsigned long long& acc, unsigned long long x,
                                      unsigned long long w)
{
    asm("fma.rn.f32x2 %0, %1, %2, %0;" : "+l"(acc) : "l"(x), "l"(w));
}
__device__ __forceinline__ unsigned long long packf2(float lo, float hi)
{
    unsigned long long r;
    asm("mov.b64 %0, {%1, %2};" : "=l"(r) : "f"(lo), "f"(hi));
    return r;
}
__device__ __forceinline__ void unpackf2(unsigned long long v, float& lo, float& hi)
{
    asm("mov.b64 {%0, %1}, %2;" : "=f"(lo), "=f"(hi) : "l"(v));
}

// ---------------- kernel 1: build qk_in (flow warps + concat) ----------------
__device__ __forceinline__ void sample32(const float* __restrict__ img, float sx, float sy,
                                         float* __restrict__ dst, int q)
{
    float x0f = floorf(sx), y0f = floorf(sy);
    float lx = sx - x0f, ly = sy - y0f;
    int x0 = (int)x0f, y0 = (int)y0f;
    float w00 = (1.f - lx) * (1.f - ly);
    float w01 = lx * (1.f - ly);
    float w10 = (1.f - lx) * ly;
    float w11 = lx * ly;
    bool vx0 = (unsigned)x0       < (unsigned)IMW;
    bool vx1 = (unsigned)(x0 + 1) < (unsigned)IMW;
    bool vy0 = (unsigned)y0       < (unsigned)IMH;
    bool vy1 = (unsigned)(y0 + 1) < (unsigned)IMH;
    int cx0 = min(max(x0, 0), IMW - 1), cx1 = min(max(x0 + 1, 0), IMW - 1);
    int cy0 = min(max(y0, 0), IMH - 1), cy1 = min(max(y0 + 1, 0), IMH - 1);
    int i00 = cy0 * IMW + cx0, i01 = cy0 * IMW + cx1;
    int i10 = cy1 * IMW + cx0, i11 = cy1 * IMW + cx1;
    float m00 = (vx0 && vy0) ? w00 : 0.f;
    float m01 = (vx1 && vy0) ? w01 : 0.f;
    float m10 = (vx0 && vy1) ? w10 : 0.f;
    float m11 = (vx1 && vy1) ? w11 : 0.f;
    #pragma unroll 4
    for (int c = 0; c < 32; ++c) {
        const float* p = img + (size_t)c * HWSZ;
        dst[(size_t)c * HWSZ + q] = m00 * p[i00] + m01 * p[i01] + m10 * p[i10] + m11 * p[i11];
    }
}

__global__ void build_qkin_kernel(const float* __restrict__ frame,
                                  const float* __restrict__ flow_f,
                                  const float* __restrict__ flow_b,
                                  float* __restrict__ qkin)
{
    int id = blockIdx.x * blockDim.x + threadIdx.x;
    if (id >= BB * HWSZ) return;
    int b = id / HWSZ, q = id % HWSZ;
    int px = q & (IMW - 1), py = q >> 8;

    const float* fb = flow_b + (size_t)b * 2 * 2 * HWSZ;
    float fbx = fb[q], fby = fb[HWSZ + q];
    const float* ff = flow_f + (size_t)b * 2 * 2 * HWSZ + (size_t)2 * HWSZ;
    float ffx = ff[q], ffy = ff[HWSZ + q];

    float* dst = qkin + (size_t)b * 100 * HWSZ;
    sample32(frame + ((size_t)b * 3 + 0) * 32 * HWSZ, (float)px + fbx, (float)py + fby, dst, q);
    const float* f1 = frame + ((size_t)b * 3 + 1) * 32 * HWSZ;
    #pragma unroll 4
    for (int c = 0; c < 32; ++c)
        dst[(size_t)(32 + c) * HWSZ + q] = f1[(size_t)c * HWSZ + q];
    sample32(frame + ((size_t)b * 3 + 2) * 32 * HWSZ, (float)px + ffx, (float)py + ffy,
             dst + (size_t)64 * HWSZ, q);
    dst[(size_t)96 * HWSZ + q] = ffx;
    dst[(size_t)97 * HWSZ + q] = ffy;
    dst[(size_t)98 * HWSZ + q] = fbx;
    dst[(size_t)99 * HWSZ + q] = fby;
}

// ---------------- cp.async helpers ----------------
__device__ __forceinline__ void cpasync4(unsigned int dst, const float* src, bool ok)
{
    int sz = ok ? 4 : 0;
    asm volatile("cp.async.ca.shared.global [%0], [%1], 4, %2;\n"
                 :: "r"(dst), "l"(src), "r"(sz));
}
__device__ __forceinline__ void cpasync_commit() {
    asm volatile("cp.async.commit_group;\n" ::: "memory");
}
__device__ __forceinline__ void cpasync_wait0() {
    asm volatile("cp.async.wait_group 0;\n" ::: "memory");
}

// ---------------- conv geometry ----------------
__host__ __device__ constexpr int cdiv_(int a, int b) { return (a + b - 1) / b; }
__host__ __device__ constexpr int convIW(int DIL)   { return 32 + 2 * DIL; }
__host__ __device__ constexpr int convIH(int DIL)   { return 16 + 2 * DIL; }
__host__ __device__ constexpr int convPPAD(int DIL)
{ return cdiv_(convIW(DIL) * convIH(DIL), 256) * 256; }
__host__ __device__ constexpr int convWPAD(int CH)
{ return cdiv_(CH * 9 * 32, 256) * 256; }
__host__ __device__ constexpr int convSmemBytes(int CH, int DIL)
{ return (2 * CH * convPPAD(DIL) + 2 * convWPAD(CH)) * 4; }

// ---------------- segment descriptor ----------------
struct Seg {
    const float* in;   size_t inStride;    // per-img input stride (elements)
    const float* in2;  size_t in2Stride;   // second input (channels >= cinA)
    int   cinA;                             // channels taken from `in`
    int   cin;
    const float* W;    const float* b;
    const float* res;  size_t resStride;   // optional residual (nullptr if none)
    float* out;        size_t outStride;
    int   cout;        int ngrp;           // ngrp = ceil(cout/32)
    int   act;                              // lrelu on output
};
struct ConvParams {
    Seg seg[3];
    int zStart[3];
    int nseg;
};

// ---------------- segmented pipelined 3x3 conv ----------------
// tile: 32(x) x 16(y) px, 32 oc per CTA; thread: 2 rows (py, py+8) x 32 oc.
// acc = f32x2 over adjacent oc pairs (FFMA2). cp.async double-buffered CH-channel chunks.
template<int CH, int DIL>
__global__ void __launch_bounds__(256, 2) conv3x3_seg(ConvParams p)
{
    constexpr int OCB = 32;
    constexpr int IW = convIW(DIL), IH = convIH(DIL);
    constexpr int PLANE = IH * IW;
    constexpr int NPF = cdiv_(PLANE, 256);
    constexpr int PPAD = NPF * 256;
    constexpr int WELEMS = CH * 9 * OCB;
    constexpr int NWF = cdiv_(WELEMS, 256);
    constexpr int WPAD = NWF * 256;

    extern __shared__ float smem[];

    const int tid = threadIdx.x;
    const int px = tid & 31, py = tid >> 5;   // px 0..31, py 0..7
    const int x0 = blockIdx.x * 32, y0 = blockIdx.y * 16;

    // segment select
    int z = blockIdx.z;
    int si = 0;
    if (p.nseg > 1 && z >= p.zStart[1]) si = 1;
    if (p.nseg > 2 && z >= p.zStart[2]) si = 2;
    z -= p.zStart[si];
    const Seg s = p.seg[si];

    const int img = z / s.ngrp;
    const int ocBase = (z % s.ngrp) * OCB;
    const int NCH = (s.cin + CH - 1) / CH;

    // ---- per-plane geometry offsets (chunk & channel invariant) ----
    unsigned int offGeo[NPF];
    #pragma unroll
    for (int j = 0; j < NPF; ++j) {
        int idx = tid + j * 256;
        unsigned int o = 0x80000000u;
        if (idx < PLANE) {
            int ly = idx / IW, lx = idx % IW;
            int gy = y0 - DIL + ly, gx = x0 - DIL + lx;
            if ((unsigned)gy < (unsigned)IMH && (unsigned)gx < (unsigned)IMW)
                o = (unsigned int)(gy * IMW + gx);
        }
        offGeo[j] = o;
    }
    // ---- weight slot offsets: bits[0:24)=offset, [24:27)=ci, [31]=invalid ----
    unsigned int offW[NWF];
    #pragma unroll
    for (int j = 0; j < NWF; ++j) {
        int idx = tid + j * 256;
        unsigned int v = 0x80000000u;
        if (idx < WELEMS) {
            int oc = idx & 31;
            int k  = (idx >> 5) % 9;
            int ci = (idx >> 5) / 9;
            if (ocBase + oc < s.cout)
                v = (unsigned int)((((ocBase + oc) * s.cin + ci) * 9) + k)
                    | ((unsigned int)ci << 24);
            else
                v = 0x80000000u | ((unsigned int)ci << 24);
        }
        offW[j] = v;
    }
    const unsigned int sBase = (unsigned int)__cvta_generic_to_shared(smem);

    unsigned long long acc[2][16];
    #pragma unroll
    for (int m = 0; m < 2; ++m)
        #pragma unroll
        for (int j = 0; j < 16; ++j) acc[m][j] = 0ULL;

    auto prefetch = [&](int cc, int b) {
        unsigned int sIn = sBase + (unsigned)(b * CH * PPAD) * 4;
        unsigned int sW  = sBase + (unsigned)((2 * CH * PPAD) + b * WPAD) * 4;
        const int chLim = s.cin - cc * CH;
        #pragma unroll
        for (int ci = 0; ci < CH; ++ci) {
            int g = cc * CH + ci;
            bool chOk = ci < chLim;
            const float* src = (g < s.cinA)
                ? s.in  + (size_t)img * s.inStride  + (size_t)g * HWSZ
                : s.in2 + (size_t)img * s.in2Stride + (size_t)(g - s.cinA) * HWSZ;
            #pragma unroll
            for (int j = 0; j < NPF; ++j) {
                unsigned int o = offGeo[j];
                bool ok = chOk && !(o & 0x80000000u);
                cpasync4(sIn + (unsigned)(ci * PPAD + tid + j * 256) * 4,
                         src + (o & 0x7FFFFFFFu), ok);
            }
        }
        const unsigned int wAdd = (unsigned int)(cc * CH) * 9u;
        #pragma unroll
        for (int j = 0; j < NWF; ++j) {
            unsigned int v = offW[j];
            int ci = (int)((v >> 24) & 7u);
            bool ok = !(v & 0x80000000u) && (ci < chLim);
            cpasync4(sW + (unsigned)(tid + j * 256) * 4,
                     s.W + (ok ? ((v & 0xFFFFFFu) + wAdd) : 0u), ok);
        }
    };

    prefetch(0, 0);
    cpasync_commit();
    cpasync_wait0();
    __syncthreads();

    int buf = 0;
    #pragma unroll 1
    for (int cc = 0; cc < NCH; ++cc) {
        if (cc + 1 < NCH) prefetch(cc + 1, buf ^ 1);
        cpasync_commit();

        const float* sI = smem + buf * CH * PPAD;
        const float* sW = smem + 2 * CH * PPAD + buf * WPAD;
        #pragma unroll 1
        for (int ci = 0; ci < CH; ++ci) {
            const float* sIc = sI + ci * PPAD;
            const float* sWc = sW + ci * 9 * OCB;
            #pragma unroll
            for (int k = 0; k < 9; ++k) {
                const int ky = k / 3, kx = k % 3;
                float xv0 = sIc[(py +     ky * DIL) * IW + px + kx * DIL];
                float xv1 = sIc[(py + 8 + ky * DIL) * IW + px + kx * DIL];
                unsigned long long xp0 = packf2(xv0, xv0);
                unsigned long long xp1 = packf2(xv1, xv1);
                const ulonglong2* wp = reinterpret_cast<const ulonglong2*>(sWc + k * OCB);
                #pragma unroll
                for (int o8 = 0; o8 < 8; ++o8) {
                    ulonglong2 w2 = wp[o8];
                    ffma2(acc[0][o8 * 2 + 0], xp0, w2.x);
                    ffma2(acc[0][o8 * 2 + 1], xp0, w2.y);
                    ffma2(acc[1][o8 * 2 + 0], xp1, w2.x);
                    ffma2(acc[1][o8 * 2 + 1], xp1, w2.y);
                }
            }
        }

        cpasync_wait0();
        __syncthreads();
        buf ^= 1;
    }

    const int ox = x0 + px;
    #pragma unroll
    for (int j = 0; j < 16; ++j) {
        int oc0 = ocBase + 2 * j;
        if (oc0 >= s.cout) continue;       // uniform per CTA (cout multiple of 16)
        float b0 = s.b[oc0];
        float b1 = s.b[oc0 + 1];
        #pragma unroll
        for (int m = 0; m < 2; ++m) {
            int oy = y0 + py + m * 8;
            float v0, v1;
            unpackf2(acc[m][j], v0, v1);
            v0 += b0;
            v1 += b1;
            if (s.res != nullptr) {
                const float* rp = s.res + (size_t)img * s.resStride;
                v0 += rp[(size_t)oc0       * HWSZ + oy * IMW + ox];
                v1 += rp[(size_t)(oc0 + 1) * HWSZ + oy * IMW + ox];
            }
            if (s.act) { v0 = lrelu(v0); v1 = lrelu(v1); }
            float* op = s.out + (size_t)img * s.outStride;
            op[(size_t)oc0       * HWSZ + oy * IMW + ox] = v0;
            op[(size_t)(oc0 + 1) * HWSZ + oy * IMW + ox] = v1;
        }
    }
}

// ---------------- deformable attention ----------------
__global__ void deform_attn_kernel(const float* __restrict__ val,
                                   const float* __restrict__ off,
                                   const float* __restrict__ awl,
                                   float* __restrict__ out)
{
    int id = blockIdx.x * blockDim.x + threadIdx.x;
    if (id >= BB * 4 * HWSZ) return;
    int q = id % HWSZ;
    int head = (id / HWSZ) & 3;
    int b = id / (4 * HWSZ);
    int px = q & (IMW - 1), py = q >> 8;

    const float* awp = awl + ((size_t)b * 48 + head * 12) * HWSZ + q;
    float lg[12];
    float mx = -1e30f;
    #pragma unroll
    for (int i = 0; i < 12; ++i) { lg[i] = awp[(size_t)i * HWSZ]; mx = fmaxf(mx, lg[i]); }
    float s = 0.f;
    #pragma unroll
    for (int i = 0; i < 12; ++i) { lg[i] = expf(lg[i] - mx); s += lg[i]; }
    float inv = 1.f / s;

    float acc[8];
    #pragma unroll
    for (int e = 0; e < 8; ++e) acc[e] = 0.f;

    const float* offp = off + ((size_t)b * 96 + head * 24) * HWSZ + q;

    for (int l = 0; l < 3; ++l) {
        const float* vbase = val + (((size_t)b * 3 + l) * 32 + head * 8) * HWSZ;
        #pragma unroll
        for (int p = 0; p < 4; ++p) {
            int ch = (l * 4 + p) * 2;
            float sx = (float)px + offp[(size_t)ch * HWSZ];
            float sy = (float)py + offp[(size_t)(ch + 1) * HWSZ];
            float a = lg[l * 4 + p] * inv;

            float x0f = floorf(sx), y0f = floorf(sy);
            float lx = sx - x0f, ly = sy - y0f;
            int x0 = (int)x0f, y0 = (int)y0f;
            float w00 = (1.f - lx) * (1.f - ly);
            float w01 = lx * (1.f - ly);
            float w10 = (1.f - lx) * ly;
            float w11 = lx * ly;
            bool vx0 = (unsigned)x0       < (unsigned)IMW;
            bool vx1 = (unsigned)(x0 + 1) < (unsigned)IMW;
            bool vy0 = (unsigned)y0       < (unsigned)IMH;
            bool vy1 = (unsigned)(y0 + 1) < (unsigned)IMH;
            int cx0 = min(max(x0, 0), IMW - 1), cx1 = min(max(x0 + 1, 0), IMW - 1);
            int cy0 = min(max(y0, 0), IMH - 1), cy1 = min(max(y0 + 1, 0), IMH - 1);
            float c00 = (vx0 && vy0) ? a * w00 : 0.f;
            float c01 = (vx1 && vy0) ? a * w01 : 0.f;
            float c10 = (vx0 && vy1) ? a * w10 : 0.f;
            float c11 = (vx1 && vy1) ? a * w11 : 0.f;
            int i00 = cy0 * IMW + cx0, i01 = cy0 * IMW + cx1;
            int i10 = cy1 * IMW + cx0, i11 = cy1 * IMW + cx1;
            #pragma unroll
            for (int e = 0; e < 8; ++e) {
                const float* vp = vbase + (size_t)e * HWSZ;
                acc[e] += c00 * vp[i00] + c01 * vp[i01] + c10 * vp[i10] + c11 * vp[i11];
            }
        }
    }

    float* op = out + ((size_t)b * 32 + head * 8) * HWSZ + q;
    #pragma unroll
    for (int e = 0; e < 8; ++e) op[(size_t)e * HWSZ] = acc[e];
}

// ---------------- final 1x1 conv + lrelu ----------------
__global__ void conv1x1_lrelu_kernel(const float* __restrict__ in,
                                     const float* __restrict__ Wt,
                                     const float* __restrict__ bias,
                                     float* __restrict__ out)
{
    __shared__ float s_w[32][32];
    __shared__ float s_b[32];
    int tid = threadIdx.x;
    for (int idx = tid; idx < 32 * 32; idx += 256)
        s_w[idx >> 5][idx & 31] = Wt[idx];
    if (tid < 32) s_b[tid] = bias[tid];
    __syncthreads();

    int id = blockIdx.x * 256 + tid;
    if (id >= BB * HWSZ) return;
    int b = id / HWSZ, q = id % HWSZ;

    float x[32];
    #pragma unroll
    for (int ci = 0; ci < 32; ++ci)
        x[ci] = in[((size_t)b * 32 + ci) * HWSZ + q];

    #pragma unroll 4
    for (int oc = 0; oc < 32; ++oc) {
        float s = s_b[oc];
        #pragma unroll
        for (int ci = 0; ci < 32; ++ci)
            s += x[ci] * s_w[oc][ci];
        out[((size_t)b * 32 + oc) * HWSZ + q] = lrelu(s);
    }
}

// ---------------- host launcher ----------------
static void fillSeg(Seg& s, const float* in, size_t inStride, int cin,
                    const float* W, const float* b, float* out, size_t outStride,
                    int cout, int act,
                    const float* res = nullptr, size_t resStride = 0,
                    const float* in2 = nullptr, size_t in2Stride = 0, int cinA = -1)
{
    s.in = in; s.inStride = inStride;
    s.in2 = in2 ? in2 : in; s.in2Stride = in2 ? in2Stride : inStride;
    s.cinA = (cinA >= 0) ? cinA : cin;
    s.cin = cin; s.W = W; s.b = b;
    s.res = res; s.resStride = resStride;
    s.out = out; s.outStride = outStride;
    s.cout = cout; s.ngrp = (cout + 31) / 32; s.act = act;
}

extern "C" void kernel_launch(void* const* d_in, const int* in_sizes, int n_in,
                              void* d_out, int out_size)
{
    const float* frame   = (const float*)d_in[0];
    const float* srcfr   = (const float*)d_in[1];
    const float* flow_f  = (const float*)d_in[2];
    const float* flow_b  = (const float*)d_in[3];
    const float* W_qk = (const float*)d_in[4];   const float* b_qk = (const float*)d_in[5];
    const float* W_v  = (const float*)d_in[6];   const float* b_v  = (const float*)d_in[7];
    const float* W_vp = (const float*)d_in[8];   const float* b_vp = (const float*)d_in[9];
    const float* W_off= (const float*)d_in[10];  const float* b_off= (const float*)d_in[11];
    const float* W_aw = (const float*)d_in[12];  const float* b_aw = (const float*)d_in[13];
    const float* W_out= (const float*)d_in[14];  const float* b_out= (const float*)d_in[15];
    const float* W_ffd= (const float*)d_in[16];  const float* b_ffd= (const float*)d_in[17];
    const float* W_ff1= (const float*)d_in[18];  const float* b_ff1= (const float*)d_in[19];
    const float* W_ff2= (const float*)d_in[20];  const float* b_ff2= (const float*)d_in[21];
    const float* W_fu = (const float*)d_in[22];  const float* b_fu = (const float*)d_in[23];

    float *qkin, *qureys, *value, *val, *off, *aw, *attn, *out1, *out2, *ff1, *out3;
    cudaGetSymbolAddress((void**)&qkin,   g_qkin);
    cudaGetSymbolAddress((void**)&qureys, g_qureys);
    cudaGetSymbolAddress((void**)&value,  g_value);
    cudaGetSymbolAddress((void**)&val,    g_val);
    cudaGetSymbolAddress((void**)&off,    g_off);
    cudaGetSymbolAddress((void**)&aw,     g_aw);
    cudaGetSymbolAddress((void**)&attn,   g_attn);
    cudaGetSymbolAddress((void**)&out1,   g_out1);
    cudaGetSymbolAddress((void**)&out2,   g_out2);
    cudaGetSymbolAddress((void**)&ff1,    g_ff1);
    cudaGetSymbolAddress((void**)&out3,   g_out3);

    constexpr int SM81 = convSmemBytes(8, 1);
    constexpr int SM82 = convSmemBytes(8, 2);

    cudaFuncSetAttribute(conv3x3_seg<8, 1>,
                         cudaFuncAttributeMaxDynamicSharedMemorySize, SM81);
    cudaFuncSetAttribute(conv3x3_seg<8, 2>,
                         cudaFuncAttributeMaxDynamicSharedMemorySize, SM82);

    const size_t H32 = (size_t)32 * HWSZ, H48 = (size_t)48 * HWSZ;
    const size_t H96 = (size_t)96 * HWSZ, H100 = (size_t)100 * HWSZ;

    // 1. qk_in
    build_qkin_kernel<<<(BB * HWSZ + 255) / 256, 256>>>(frame, flow_f, flow_b, qkin);

    // 2. merged: qureys = lrelu(conv(qkin,W_qk)) [z 0..5] ; value = conv(frame,W_v) [z 6..11]
    {
        ConvParams p{};
        fillSeg(p.seg[0], qkin, H100, 100, W_qk, b_qk, qureys, H96, 96, 1);
        fillSeg(p.seg[1], frame, H96,  96,  W_v,  b_v,  value,  H96, 96, 0);
        p.zStart[0] = 0; p.zStart[1] = BB * 3; p.nseg = 2;
        conv3x3_seg<8, 1><<<dim3(8, 16, BB * 6), 256, SM81>>>(p);
    }

    // 3. merged: val = conv(value,W_vp) [6 imgs, z 0..5] ; off [z 6..11] ; aw [z 12..15]
    {
        ConvParams p{};
        fillSeg(p.seg[0], value,  H32, 32, W_vp,  b_vp,  val, H32, 32, 0);
        fillSeg(p.seg[1], qureys, H96, 96, W_off, b_off, off, H96, 96, 0);
        fillSeg(p.seg[2], qureys, H96, 96, W_aw,  b_aw,  aw,  H48, 48, 0);
        p.zStart[0] = 0; p.zStart[1] = 6; p.zStart[2] = 6 + BB * 3;
        p.nseg = 3;
        conv3x3_seg<8, 1><<<dim3(8, 16, 6 + BB * 3 + BB * 2), 256, SM81>>>(p);
    }

    // 4. deformable attention
    deform_attn_kernel<<<(BB * 4 * HWSZ + 255) / 256, 256>>>(val, off, aw, attn);

    // 5. out1 = conv(attn, W_out)
    {
        ConvParams p{};
        fillSeg(p.seg[0], attn, H32, 32, W_out, b_out, out1, H32, 32, 0);
        p.zStart[0] = 0; p.nseg = 1;
        conv3x3_seg<8, 1><<<dim3(8, 16, BB), 256, SM81>>>(p);
    }

    // 6. out2 = conv(out1, W_ffd) + frame[:,1]
    {
        ConvParams p{};
        fillSeg(p.seg[0], out1, H32, 32, W_ffd, b_ffd, out2, H32, 32, 0,
                frame + H32, H96);
        p.zStart[0] = 0; p.nseg = 1;
        conv3x3_seg<8, 1><<<dim3(8, 16, BB), 256, SM81>>>(p);
    }

    // 7. ff1 = lrelu(conv([out2, srcframe[:,1]], W_ff1, pad=2, dil=2))  (fused concat)
    {
        ConvParams p{};
        fillSeg(p.seg[0], out2, H32, 64, W_ff1, b_ff1, ff1, H32, 32, 1,
                nullptr, 0, srcfr + H32, H96, 32);
        p.zStart[0] = 0; p.nseg = 1;
        conv3x3_seg<8, 2><<<dim3(8, 16, BB), 256, SM82>>>(p);
    }

    // 8. out3 = conv(ff1, W_ff2) + out2
    {
        ConvParams p{};
        fillSeg(p.seg[0], ff1, H32, 32, W_ff2, b_ff2, out3, H32, 32, 0,
                out2, H32);
        p.zStart[0] = 0; p.nseg = 1;
        conv3x3_seg<8, 1><<<dim3(8, 16, BB), 256, SM81>>>(p);
    }

    // 9. out = lrelu(conv1x1(out3, W_fu))
    conv1x1_lrelu_kernel<<<(BB * HWSZ + 255) / 256, 256>>>(out3, W_fu, b_fu, (float*)d_out);
}

// round 14
// speedup vs baseline: 1.2364x; 1.2364x over previous
#include <cuda_runtime.h>
#include <cstdint>
#include <math.h>

constexpr int IMH = 256, IMW = 256;
constexpr int HWSZ = IMH * IMW;       // 65536
constexpr int BB = 2;

// ---------------- scratch (device globals; no runtime allocation) ----------------
__device__ float g_qkin  [(size_t)BB * 100 * HWSZ];
__device__ float g_qureys[(size_t)BB *  96 * HWSZ];
__device__ float g_value [(size_t)BB *  96 * HWSZ];
__device__ float g_val   [(size_t)BB *  96 * HWSZ];
__device__ float g_off   [(size_t)BB *  96 * HWSZ];
__device__ float g_aw    [(size_t)BB *  48 * HWSZ];
__device__ float g_attn  [(size_t)BB *  32 * HWSZ];
__device__ float g_out1  [(size_t)BB *  32 * HWSZ];
__device__ float g_out2  [(size_t)BB *  32 * HWSZ];
__device__ float g_ff1   [(size_t)BB *  32 * HWSZ];
__device__ float g_out3  [(size_t)BB *  32 * HWSZ];

__device__ __forceinline__ float lrelu(float v) { return v >= 0.f ? v : 0.1f * v; }

// ---------------- packed f32x2 helpers (Blackwell FFMA2) ----------------
__device__ __forceinline__ void ffma2(unsigned long long& acc, unsigned long long x,
                                      unsigned long long w)
{
    asm("fma.rn.f32x2 %0, %1, %2, %0;" : "+l"(acc) : "l"(x), "l"(w));
}
__device__ __forceinline__ unsigned long long packf2(float lo, float hi)
{
    unsigned long long r;
    asm("mov.b64 %0, {%1, %2};" : "=l"(r) : "f"(lo), "f"(hi));
    return r;
}
__device__ __forceinline__ void unpackf2(unsigned long long v, float& lo, float& hi)
{
    asm("mov.b64 {%0, %1}, %2;" : "=f"(lo), "=f"(hi) : "l"(v));
}

// ---------------- kernel 1: build qk_in (flow warps + concat) ----------------
__device__ __forceinline__ void sample32(const float* __restrict__ img, float sx, float sy,
                                         float* __restrict__ dst, int q)
{
    float x0f = floorf(sx), y0f = floorf(sy);
    float lx = sx - x0f, ly = sy - y0f;
    int x0 = (int)x0f, y0 = (int)y0f;
    float w00 = (1.f - lx) * (1.f - ly);
    float w01 = lx * (1.f - ly);
    float w10 = (1.f - lx) * ly;
    float w11 = lx * ly;
    bool vx0 = (unsigned)x0       < (unsigned)IMW;
    bool vx1 = (unsigned)(x0 + 1) < (unsigned)IMW;
    bool vy0 = (unsigned)y0       < (unsigned)IMH;
    bool vy1 = (unsigned)(y0 + 1) < (unsigned)IMH;
    int cx0 = min(max(x0, 0), IMW - 1), cx1 = min(max(x0 + 1, 0), IMW - 1);
    int cy0 = min(max(y0, 0), IMH - 1), cy1 = min(max(y0 + 1, 0), IMH - 1);
    int i00 = cy0 * IMW + cx0, i01 = cy0 * IMW + cx1;
    int i10 = cy1 * IMW + cx0, i11 = cy1 * IMW + cx1;
    float m00 = (vx0 && vy0) ? w00 : 0.f;
    float m01 = (vx1 && vy0) ? w01 : 0.f;
    float m10 = (vx0 && vy1) ? w10 : 0.f;
    float m11 = (vx1 && vy1) ? w11 : 0.f;
    #pragma unroll 4
    for (int c = 0; c < 32; ++c) {
        const float* p = img + (size_t)c * HWSZ;
        dst[(size_t)c * HWSZ + q] = m00 * p[i00] + m01 * p[i01] + m10 * p[i10] + m11 * p[i11];
    }
}

__global__ void build_qkin_kernel(const float* __restrict__ frame,
                                  const float* __restrict__ flow_f,
                                  const float* __restrict__ flow_b,
                                  float* __restrict__ qkin)
{
    int id = blockIdx.x * blockDim.x + threadIdx.x;
    if (id >= BB * HWSZ) return;
    int b = id / HWSZ, q = id % HWSZ;
    int px = q & (IMW - 1), py = q >> 8;

    const float* fb = flow_b + (size_t)b * 2 * 2 * HWSZ;
    float fbx = fb[q], fby = fb[HWSZ + q];
    const float* ff = flow_f + (size_t)b * 2 * 2 * HWSZ + (size_t)2 * HWSZ;
    float ffx = ff[q], ffy = ff[HWSZ + q];

    float* dst = qkin + (size_t)b * 100 * HWSZ;
    sample32(frame + ((size_t)b * 3 + 0) * 32 * HWSZ, (float)px + fbx, (float)py + fby, dst, q);
    const float* f1 = frame + ((size_t)b * 3 + 1) * 32 * HWSZ;
    #pragma unroll 4
    for (int c = 0; c < 32; ++c)
        dst[(size_t)(32 + c) * HWSZ + q] = f1[(size_t)c * HWSZ + q];
    sample32(frame + ((size_t)b * 3 + 2) * 32 * HWSZ, (float)px + ffx, (float)py + ffy,
             dst + (size_t)64 * HWSZ, q);
    dst[(size_t)96 * HWSZ + q] = ffx;
    dst[(size_t)97 * HWSZ + q] = ffy;
    dst[(size_t)98 * HWSZ + q] = fbx;
    dst[(size_t)99 * HWSZ + q] = fby;
}

// ---------------- cp.async helpers ----------------
__device__ __forceinline__ void cpasync4(unsigned int dst, const float* src, bool ok)
{
    int sz = ok ? 4 : 0;
    asm volatile("cp.async.ca.shared.global [%0], [%1], 4, %2;\n"
                 :: "r"(dst), "l"(src), "r"(sz));
}
__device__ __forceinline__ void cpasync_commit() {
    asm volatile("cp.async.commit_group;\n" ::: "memory");
}
__device__ __forceinline__ void cpasync_wait0() {
    asm volatile("cp.async.wait_group 0;\n" ::: "memory");
}

// ---------------- conv geometry (32x32 tile) ----------------
__host__ __device__ constexpr int cdiv_(int a, int b) { return (a + b - 1) / b; }
__host__ __device__ constexpr int convIW(int DIL)   { return 32 + 2 * DIL; }
__host__ __device__ constexpr int convPPAD(int DIL)
{ return cdiv_(convIW(DIL) * convIW(DIL), 256) * 256; }
__host__ __device__ constexpr int convWPAD(int CH)
{ return cdiv_(CH * 9 * 16, 256) * 256; }
__host__ __device__ constexpr int convSmemBytes(int CH, int DIL)
{ return (2 * CH * convPPAD(DIL) + 2 * convWPAD(CH)) * 4; }

// ---------------- segment descriptor ----------------
struct Seg {
    const float* in;   size_t inStride;
    const float* in2;  size_t in2Stride;   // channels >= cinA come from in2
    int   cinA;
    int   cin;
    const float* W;    const float* b;
    const float* res;  size_t resStride;
    float* out;        size_t outStride;
    int   cout;        int ngrp;           // ngrp = cout/16
    int   act;
};
struct ConvParams {
    Seg seg[3];
    int zStart[3];
    int nseg;
};

// ---------------- segmented pipelined 3x3 conv (R12 core) ----------------
// tile: 32x32 px, 16 oc per CTA; thread: 4 rows (py+8m) x 16 oc, f32x2 oc-pairs.
template<int CH, int DIL>
__global__ void __launch_bounds__(256, 2) conv3x3_seg(ConvParams p)
{
    constexpr int OCB = 16;
    constexpr int IW = convIW(DIL), IH = IW;
    constexpr int PLANE = IH * IW;
    constexpr int NPF = cdiv_(PLANE, 256);
    constexpr int PPAD = NPF * 256;
    constexpr int WELEMS = CH * 9 * OCB;
    constexpr int NWF = cdiv_(WELEMS, 256);
    constexpr int WPAD = NWF * 256;

    extern __shared__ float smem[];

    const int tid = threadIdx.x;
    const int px = tid & 31, py = tid >> 5;   // px 0..31, py 0..7
    const int x0 = blockIdx.x * 32, y0 = blockIdx.y * 32;

    // segment select
    int z = blockIdx.z;
    int si = 0;
    if (p.nseg > 1 && z >= p.zStart[1]) si = 1;
    if (p.nseg > 2 && z >= p.zStart[2]) si = 2;
    z -= p.zStart[si];
    const Seg s = p.seg[si];

    const int img = z / s.ngrp;
    const int ocBase = (z % s.ngrp) * OCB;
    const int NCH = (s.cin + CH - 1) / CH;

    // ---- per-plane geometry offsets ----
    unsigned int offGeo[NPF];
    #pragma unroll
    for (int j = 0; j < NPF; ++j) {
        int idx = tid + j * 256;
        unsigned int o = 0x80000000u;
        if (idx < PLANE) {
            int ly = idx / IW, lx = idx % IW;
            int gy = y0 - DIL + ly, gx = x0 - DIL + lx;
            if ((unsigned)gy < (unsigned)IMH && (unsigned)gx < (unsigned)IMW)
                o = (unsigned int)(gy * IMW + gx);
        }
        offGeo[j] = o;
    }
    // ---- weight slot offsets ----
    unsigned int offW[NWF];
    int ciSlotW[NWF];
    #pragma unroll
    for (int j = 0; j < NWF; ++j) {
        int idx = tid + j * 256;
        if (idx < WELEMS) {
            int oc = idx & 15;
            int k  = (idx >> 4) % 9;
            int ci = (idx >> 4) / 9;
            offW[j] = (unsigned int)(((ocBase + oc) * s.cin + ci) * 9 + k);
            ciSlotW[j] = ci;
        } else { offW[j] = 0; ciSlotW[j] = 0x7FFFFFF; }
    }
    const unsigned int sBase = (unsigned int)__cvta_generic_to_shared(smem);

    unsigned long long acc[4][8];
    #pragma unroll
    for (int m = 0; m < 4; ++m)
        #pragma unroll
        for (int j = 0; j < 8; ++j) acc[m][j] = 0ULL;

    auto prefetch = [&](int cc, int b) {
        unsigned int sIn = sBase + (unsigned)(b * CH * PPAD) * 4;
        unsigned int sW  = sBase + (unsigned)((2 * CH * PPAD) + b * WPAD) * 4;
        const int chLim = s.cin - cc * CH;
        #pragma unroll
        for (int ci = 0; ci < CH; ++ci) {
            int g = cc * CH + ci;
            bool chOk = ci < chLim;
            const float* src = (g < s.cinA)
                ? s.in  + (size_t)img * s.inStride  + (size_t)g * HWSZ
                : s.in2 + (size_t)img * s.in2Stride + (size_t)(g - s.cinA) * HWSZ;
            #pragma unroll
            for (int j = 0; j < NPF; ++j) {
                unsigned int o = offGeo[j];
                bool ok = chOk && !(o & 0x80000000u);
                cpasync4(sIn + (unsigned)(ci * PPAD + tid + j * 256) * 4,
                         src + (o & 0x7FFFFFFFu), ok);
            }
        }
        const unsigned int wAdd = (unsigned int)(cc * CH) * 9u;
        #pragma unroll
        for (int j = 0; j < NWF; ++j) {
            bool ok = ciSlotW[j] < chLim;
            cpasync4(sW + (unsigned)(tid + j * 256) * 4,
                     s.W + (ok ? (offW[j] + wAdd) : 0u), ok);
        }
    };

    prefetch(0, 0);
    cpasync_commit();
    cpasync_wait0();
    __syncthreads();

    int buf = 0;
    #pragma unroll 1
    for (int cc = 0; cc < NCH; ++cc) {
        if (cc + 1 < NCH) prefetch(cc + 1, buf ^ 1);
        cpasync_commit();

        const float* sI = smem + buf * CH * PPAD;
        const float* sW = smem + 2 * CH * PPAD + buf * WPAD;
        #pragma unroll 1
        for (int ci = 0; ci < CH; ++ci) {
            const float* sIc = sI + ci * PPAD;
            const float* sWc = sW + ci * 9 * OCB;
            #pragma unroll
            for (int k = 0; k < 9; ++k) {
                const int ky = k / 3, kx = k % 3;
                unsigned long long xp[4];
                #pragma unroll
                for (int m = 0; m < 4; ++m) {
                    float xv = sIc[(py + m * 8 + ky * DIL) * IW + px + kx * DIL];
                    xp[m] = packf2(xv, xv);
                }
                const ulonglong2* wp = reinterpret_cast<const ulonglong2*>(sWc + k * OCB);
                #pragma unroll
                for (int o4 = 0; o4 < 4; ++o4) {
                    ulonglong2 w2 = wp[o4];
                    #pragma unroll
                    for (int m = 0; m < 4; ++m) {
                        ffma2(acc[m][o4 * 2 + 0], xp[m], w2.x);
                        ffma2(acc[m][o4 * 2 + 1], xp[m], w2.y);
                    }
                }
            }
        }

        cpasync_wait0();
        __syncthreads();
        buf ^= 1;
    }

    const int ox = x0 + px;
    float* op = s.out + (size_t)img * s.outStride;
    #pragma unroll
    for (int j = 0; j < 8; ++j) {
        int oc0 = ocBase + 2 * j;
        float b0 = s.b[oc0];
        float b1 = s.b[oc0 + 1];
        #pragma unroll
        for (int m = 0; m < 4; ++m) {
            int oy = y0 + py + m * 8;
            float v0, v1;
            unpackf2(acc[m][j], v0, v1);
            v0 += b0;
            v1 += b1;
            if (s.res != nullptr) {
                const float* rp = s.res + (size_t)img * s.resStride;
                v0 += rp[(size_t)oc0       * HWSZ + oy * IMW + ox];
                v1 += rp[(size_t)(oc0 + 1) * HWSZ + oy * IMW + ox];
            }
            if (s.act) { v0 = lrelu(v0); v1 = lrelu(v1); }
            op[(size_t)oc0       * HWSZ + oy * IMW + ox] = v0;
            op[(size_t)(oc0 + 1) * HWSZ + oy * IMW + ox] = v1;
        }
    }
}

// ---------------- deformable attention ----------------
__global__ void deform_attn_kernel(const float* __restrict__ val,
                                   const float* __restrict__ off,
                                   const float* __restrict__ awl,
                                   float* __restrict__ out)
{
    int id = blockIdx.x * blockDim.x + threadIdx.x;
    if (id >= BB * 4 * HWSZ) return;
    int q = id % HWSZ;
    int head = (id / HWSZ) & 3;
    int b = id / (4 * HWSZ);
    int px = q & (IMW - 1), py = q >> 8;

    const float* awp = awl + ((size_t)b * 48 + head * 12) * HWSZ + q;
    float lg[12];
    float mx = -1e30f;
    #pragma unroll
    for (int i = 0; i < 12; ++i) { lg[i] = awp[(size_t)i * HWSZ]; mx = fmaxf(mx, lg[i]); }
    float s = 0.f;
    #pragma unroll
    for (int i = 0; i < 12; ++i) { lg[i] = expf(lg[i] - mx); s += lg[i]; }
    float inv = 1.f / s;

    float acc[8];
    #pragma unroll
    for (int e = 0; e < 8; ++e) acc[e] = 0.f;

    const float* offp = off + ((size_t)b * 96 + head * 24) * HWSZ + q;

    for (int l = 0; l < 3; ++l) {
        const float* vbase = val + (((size_t)b * 3 + l) * 32 + head * 8) * HWSZ;
        #pragma unroll
        for (int p = 0; p < 4; ++p) {
            int ch = (l * 4 + p) * 2;
            float sx = (float)px + offp[(size_t)ch * HWSZ];
            float sy = (float)py + offp[(size_t)(ch + 1) * HWSZ];
            float a = lg[l * 4 + p] * inv;

            float x0f = floorf(sx), y0f = floorf(sy);
            float lx = sx - x0f, ly = sy - y0f;
            int x0 = (int)x0f, y0 = (int)y0f;
            float w00 = (1.f - lx) * (1.f - ly);
            float w01 = lx * (1.f - ly);
            float w10 = (1.f - lx) * ly;
            float w11 = lx * ly;
            bool vx0 = (unsigned)x0       < (unsigned)IMW;
            bool vx1 = (unsigned)(x0 + 1) < (unsigned)IMW;
            bool vy0 = (unsigned)y0       < (unsigned)IMH;
            bool vy1 = (unsigned)(y0 + 1) < (unsigned)IMH;
            int cx0 = min(max(x0, 0), IMW - 1), cx1 = min(max(x0 + 1, 0), IMW - 1);
            int cy0 = min(max(y0, 0), IMH - 1), cy1 = min(max(y0 + 1, 0), IMH - 1);
            float c00 = (vx0 && vy0) ? a * w00 : 0.f;
            float c01 = (vx1 && vy0) ? a * w01 : 0.f;
            float c10 = (vx0 && vy1) ? a * w10 : 0.f;
            float c11 = (vx1 && vy1) ? a * w11 : 0.f;
            int i00 = cy0 * IMW + cx0, i01 = cy0 * IMW + cx1;
            int i10 = cy1 * IMW + cx0, i11 = cy1 * IMW + cx1;
            #pragma unroll
            for (int e = 0; e < 8; ++e) {
                const float* vp = vbase + (size_t)e * HWSZ;
                acc[e] += c00 * vp[i00] + c01 * vp[i01] + c10 * vp[i10] + c11 * vp[i11];
            }
        }
    }

    float* op = out + ((size_t)b * 32 + head * 8) * HWSZ + q;
    #pragma unroll
    for (int e = 0; e < 8; ++e) op[(size_t)e * HWSZ] = acc[e];
}

// ---------------- final 1x1 conv + lrelu ----------------
__global__ void conv1x1_lrelu_kernel(const float* __restrict__ in,
                                     const float* __restrict__ Wt,
                                     const float* __restrict__ bias,
                                     float* __restrict__ out)
{
    __shared__ float s_w[32][32];
    __shared__ float s_b[32];
    int tid = threadIdx.x;
    for (int idx = tid; idx < 32 * 32; idx += 256)
        s_w[idx >> 5][idx & 31] = Wt[idx];
    if (tid < 32) s_b[tid] = bias[tid];
    __syncthreads();

    int id = blockIdx.x * 256 + tid;
    if (id >= BB * HWSZ) return;
    int b = id / HWSZ, q = id % HWSZ;

    float x[32];
    #pragma unroll
    for (int ci = 0; ci < 32; ++ci)
        x[ci] = in[((size_t)b * 32 + ci) * HWSZ + q];

    #pragma unroll 4
    for (int oc = 0; oc < 32; ++oc) {
        float s = s_b[oc];
        #pragma unroll
        for (int ci = 0; ci < 32; ++ci)
            s += x[ci] * s_w[oc][ci];
        out[((size_t)b * 32 + oc) * HWSZ + q] = lrelu(s);
    }
}

// ---------------- host launcher ----------------
static void fillSeg(Seg& s, const float* in, size_t inStride, int cin,
                    const float* W, const float* b, float* out, size_t outStride,
                    int cout, int act,
                    const float* res = nullptr, size_t resStride = 0,
                    const float* in2 = nullptr, size_t in2Stride = 0, int cinA = -1)
{
    s.in = in; s.inStride = inStride;
    s.in2 = in2 ? in2 : in; s.in2Stride = in2 ? in2Stride : inStride;
    s.cinA = (cinA >= 0) ? cinA : cin;
    s.cin = cin; s.W = W; s.b = b;
    s.res = res; s.resStride = resStride;
    s.out = out; s.outStride = outStride;
    s.cout = cout; s.ngrp = cout / 16; s.act = act;
}

extern "C" void kernel_launch(void* const* d_in, const int* in_sizes, int n_in,
                              void* d_out, int out_size)
{
    const float* frame   = (const float*)d_in[0];
    const float* srcfr   = (const float*)d_in[1];
    const float* flow_f  = (const float*)d_in[2];
    const float* flow_b  = (const float*)d_in[3];
    const float* W_qk = (const float*)d_in[4];   const float* b_qk = (const float*)d_in[5];
    const float* W_v  = (const float*)d_in[6];   const float* b_v  = (const float*)d_in[7];
    const float* W_vp = (const float*)d_in[8];   const float* b_vp = (const float*)d_in[9];
    const float* W_off= (const float*)d_in[10];  const float* b_off= (const float*)d_in[11];
    const float* W_aw = (const float*)d_in[12];  const float* b_aw = (const float*)d_in[13];
    const float* W_out= (const float*)d_in[14];  const float* b_out= (const float*)d_in[15];
    const float* W_ffd= (const float*)d_in[16];  const float* b_ffd= (const float*)d_in[17];
    const float* W_ff1= (const float*)d_in[18];  const float* b_ff1= (const float*)d_in[19];
    const float* W_ff2= (const float*)d_in[20];  const float* b_ff2= (const float*)d_in[21];
    const float* W_fu = (const float*)d_in[22];  const float* b_fu = (const float*)d_in[23];

    float *qkin, *qureys, *value, *val, *off, *aw, *attn, *out1, *out2, *ff1, *out3;
    cudaGetSymbolAddress((void**)&qkin,   g_qkin);
    cudaGetSymbolAddress((void**)&qureys, g_qureys);
    cudaGetSymbolAddress((void**)&value,  g_value);
    cudaGetSymbolAddress((void**)&val,    g_val);
    cudaGetSymbolAddress((void**)&off,    g_off);
    cudaGetSymbolAddress((void**)&aw,     g_aw);
    cudaGetSymbolAddress((void**)&attn,   g_attn);
    cudaGetSymbolAddress((void**)&out1,   g_out1);
    cudaGetSymbolAddress((void**)&out2,   g_out2);
    cudaGetSymbolAddress((void**)&ff1,    g_ff1);
    cudaGetSymbolAddress((void**)&out3,   g_out3);

    constexpr int SM81 = convSmemBytes(8, 1);   // 92160
    constexpr int SM82 = convSmemBytes(8, 2);   // 108544

    cudaFuncSetAttribute(conv3x3_seg<8, 1>,
                         cudaFuncAttributeMaxDynamicSharedMemorySize, SM81);
    cudaFuncSetAttribute(conv3x3_seg<8, 2>,
                         cudaFuncAttributeMaxDynamicSharedMemorySize, SM82);

    const size_t H32 = (size_t)32 * HWSZ, H48 = (size_t)48 * HWSZ;
    const size_t H96 = (size_t)96 * HWSZ, H100 = (size_t)100 * HWSZ;

    // 1. qk_in
    build_qkin_kernel<<<(BB * HWSZ + 255) / 256, 256>>>(frame, flow_f, flow_b, qkin);

    // 2. merged: qureys = lrelu(conv(qkin,W_qk)) ; value = conv(frame,W_v)
    {
        ConvParams p{};
        fillSeg(p.seg[0], qkin, H100, 100, W_qk, b_qk, qureys, H96, 96, 1);
        fillSeg(p.seg[1], frame, H96,  96,  W_v,  b_v,  value,  H96, 96, 0);
        p.zStart[0] = 0; p.zStart[1] = BB * 6; p.nseg = 2;
        conv3x3_seg<8, 1><<<dim3(8, 8, BB * 12), 256, SM81>>>(p);
    }

    // 3. merged: val (6 imgs x 2 grp) ; off (BB x 6 grp) ; aw (BB x 3 grp)
    {
        ConvParams p{};
        fillSeg(p.seg[0], value,  H32, 32, W_vp,  b_vp,  val, H32, 32, 0);
        fillSeg(p.seg[1], qureys, H96, 96, W_off, b_off, off, H96, 96, 0);
        fillSeg(p.seg[2], qureys, H96, 96, W_aw,  b_aw,  aw,  H48, 48, 0);
        p.zStart[0] = 0; p.zStart[1] = 12; p.zStart[2] = 12 + BB * 6;
        p.nseg = 3;
        conv3x3_seg<8, 1><<<dim3(8, 8, 12 + BB * 6 + BB * 3), 256, SM81>>>(p);
    }

    // 4. deformable attention
    deform_attn_kernel<<<(BB * 4 * HWSZ + 255) / 256, 256>>>(val, off, aw, attn);

    // 5. out1 = conv(attn, W_out)
    {
        ConvParams p{};
        fillSeg(p.seg[0], attn, H32, 32, W_out, b_out, out1, H32, 32, 0);
        p.zStart[0] = 0; p.nseg = 1;
        conv3x3_seg<8, 1><<<dim3(8, 8, BB * 2), 256, SM81>>>(p);
    }

    // 6. out2 = conv(out1, W_ffd) + frame[:,1]
    {
        ConvParams p{};
        fillSeg(p.seg[0], out1, H32, 32, W_ffd, b_ffd, out2, H32, 32, 0,
                frame + H32, H96);
        p.zStart[0] = 0; p.nseg = 1;
        conv3x3_seg<8, 1><<<dim3(8, 8, BB * 2), 256, SM81>>>(p);
    }

    // 7. ff1 = lrelu(conv([out2, srcframe[:,1]], W_ff1, pad=2, dil=2))  (fused concat)
    {
        ConvParams p{};
        fillSeg(p.seg[0], out2, H32, 64, W_ff1, b_ff1, ff1, H32, 32, 1,
                nullptr, 0, srcfr + H32, H96, 32);
        p.zStart[0] = 0; p.nseg = 1;
        conv3x3_seg<8, 2><<<dim3(8, 8, BB * 2), 256, SM82>>>(p);
    }

    // 8. out3 = conv(ff1, W_ff2) + out2
    {
        ConvParams p{};
        fillSeg(p.seg[0], ff1, H32, 32, W_ff2, b_ff2, out3, H32, 32, 0,
                out2, H32);
        p.zStart[0] = 0; p.nseg = 1;
        conv3x3_seg<8, 1><<<dim3(8, 8, BB * 2), 256, SM81>>>(p);
    }

    // 9. out = lrelu(conv1x1(out3, W_fu))
    conv1x1_lrelu_kernel<<<(BB * HWSZ + 255) / 256, 256>>>(out3, W_fu, b_fu, (float*)d_out);
}

// round 15
// speedup vs baseline: 1.3858x; 1.1208x over previous
#include <cuda_runtime.h>
#include <cstdint>
#include <math.h>

constexpr int IMH = 256, IMW = 256;
constexpr int HWSZ = IMH * IMW;       // 65536
constexpr int BB = 2;

// ---------------- scratch (device globals; no runtime allocation) ----------------
__device__ float g_qkin  [(size_t)BB * 100 * HWSZ];
__device__ float g_qureys[(size_t)BB *  96 * HWSZ];
__device__ float g_value [(size_t)BB *  96 * HWSZ];
__device__ float g_val   [(size_t)BB *  96 * HWSZ];
__device__ float g_off   [(size_t)BB *  96 * HWSZ];
__device__ float g_aw    [(size_t)BB *  48 * HWSZ];
__device__ float g_attn  [(size_t)BB *  32 * HWSZ];
__device__ float g_out1  [(size_t)BB *  32 * HWSZ];
__device__ float g_out2  [(size_t)BB *  32 * HWSZ];
__device__ float g_ff1   [(size_t)BB *  32 * HWSZ];
__device__ float g_out3  [(size_t)BB *  32 * HWSZ];

__device__ __forceinline__ float lrelu(float v) { return v >= 0.f ? v : 0.1f * v; }

// ---------------- packed f32x2 helpers (Blackwell FFMA2) ----------------
__device__ __forceinline__ void ffma2(unsigned long long& acc, unsigned long long x,
                                      unsigned long long w)
{
    asm("fma.rn.f32x2 %0, %1, %2, %0;" : "+l"(acc) : "l"(x), "l"(w));
}
__device__ __forceinline__ unsigned long long packf2(float lo, float hi)
{
    unsigned long long r;
    asm("mov.b64 %0, {%1, %2};" : "=l"(r) : "f"(lo), "f"(hi));
    return r;
}
__device__ __forceinline__ void unpackf2(unsigned long long v, float& lo, float& hi)
{
    asm("mov.b64 {%0, %1}, %2;" : "=f"(lo), "=f"(hi) : "l"(v));
}

// ---------------- kernel 1: build qk_in (flow warps + concat) ----------------
__device__ __forceinline__ void sample32(const float* __restrict__ img, float sx, float sy,
                                         float* __restrict__ dst, int q)
{
    float x0f = floorf(sx), y0f = floorf(sy);
    float lx = sx - x0f, ly = sy - y0f;
    int x0 = (int)x0f, y0 = (int)y0f;
    float w00 = (1.f - lx) * (1.f - ly);
    float w01 = lx * (1.f - ly);
    float w10 = (1.f - lx) * ly;
    float w11 = lx * ly;
    bool vx0 = (unsigned)x0       < (unsigned)IMW;
    bool vx1 = (unsigned)(x0 + 1) < (unsigned)IMW;
    bool vy0 = (unsigned)y0       < (unsigned)IMH;
    bool vy1 = (unsigned)(y0 + 1) < (unsigned)IMH;
    int cx0 = min(max(x0, 0), IMW - 1), cx1 = min(max(x0 + 1, 0), IMW - 1);
    int cy0 = min(max(y0, 0), IMH - 1), cy1 = min(max(y0 + 1, 0), IMH - 1);
    int i00 = cy0 * IMW + cx0, i01 = cy0 * IMW + cx1;
    int i10 = cy1 * IMW + cx0, i11 = cy1 * IMW + cx1;
    float m00 = (vx0 && vy0) ? w00 : 0.f;
    float m01 = (vx1 && vy0) ? w01 : 0.f;
    float m10 = (vx0 && vy1) ? w10 : 0.f;
    float m11 = (vx1 && vy1) ? w11 : 0.f;
    #pragma unroll 4
    for (int c = 0; c < 32; ++c) {
        const float* p = img + (size_t)c * HWSZ;
        dst[(size_t)c * HWSZ + q] = m00 * p[i00] + m01 * p[i01] + m10 * p[i10] + m11 * p[i11];
    }
}

__global__ void build_qkin_kernel(const float* __restrict__ frame,
                                  const float* __restrict__ flow_f,
                                  const float* __restrict__ flow_b,
                                  float* __restrict__ qkin)
{
    int id = blockIdx.x * blockDim.x + threadIdx.x;
    if (id >= BB * HWSZ) return;
    int b = id / HWSZ, q = id % HWSZ;
    int px = q & (IMW - 1), py = q >> 8;

    const float* fb = flow_b + (size_t)b * 2 * 2 * HWSZ;
    float fbx = fb[q], fby = fb[HWSZ + q];
    const float* ff = flow_f + (size_t)b * 2 * 2 * HWSZ + (size_t)2 * HWSZ;
    float ffx = ff[q], ffy = ff[HWSZ + q];

    float* dst = qkin + (size_t)b * 100 * HWSZ;
    sample32(frame + ((size_t)b * 3 + 0) * 32 * HWSZ, (float)px + fbx, (float)py + fby, dst, q);
    const float* f1 = frame + ((size_t)b * 3 + 1) * 32 * HWSZ;
    #pragma unroll 4
    for (int c = 0; c < 32; ++c)
        dst[(size_t)(32 + c) * HWSZ + q] = f1[(size_t)c * HWSZ + q];
    sample32(frame + ((size_t)b * 3 + 2) * 32 * HWSZ, (float)px + ffx, (float)py + ffy,
             dst + (size_t)64 * HWSZ, q);
    dst[(size_t)96 * HWSZ + q] = ffx;
    dst[(size_t)97 * HWSZ + q] = ffy;
    dst[(size_t)98 * HWSZ + q] = fbx;
    dst[(size_t)99 * HWSZ + q] = fby;
}

// ---------------- cp.async helpers ----------------
__device__ __forceinline__ void cpasync4(unsigned int dst, const float* src, bool ok)
{
    int sz = ok ? 4 : 0;
    asm volatile("cp.async.ca.shared.global [%0], [%1], 4, %2;\n"
                 :: "r"(dst), "l"(src), "r"(sz));
}
__device__ __forceinline__ void cpasync_commit() {
    asm volatile("cp.async.commit_group;\n" ::: "memory");
}
__device__ __forceinline__ void cpasync_wait0() {
    asm volatile("cp.async.wait_group 0;\n" ::: "memory");
}

// ---------------- conv geometry (32x32 tile, row stride 36 for LDS.128 alignment) ----------------
__host__ __device__ constexpr int cdiv_(int a, int b) { return (a + b - 1) / b; }
constexpr int RS = 36;                                  // padded row stride (144 B = 9x16B)
__host__ __device__ constexpr int convIW(int DIL)   { return 32 + 2 * DIL; }
__host__ __device__ constexpr int convIH(int DIL)   { return 32 + 2 * DIL; }
__host__ __device__ constexpr int convPPAD(int DIL)
{ return cdiv_(convIH(DIL) * RS, 256) * 256; }
__host__ __device__ constexpr int convWPAD(int CH)
{ return cdiv_(CH * 9 * 16, 256) * 256; }
__host__ __device__ constexpr int convSmemBytes(int CH, int DIL)
{ return (2 * CH * convPPAD(DIL) + 2 * convWPAD(CH)) * 4; }

// ---------------- segment descriptor ----------------
struct Seg {
    const float* in;   size_t inStride;
    const float* in2;  size_t in2Stride;   // channels >= cinA come from in2
    int   cinA;
    int   cin;
    const float* W;    const float* b;
    const float* res;  size_t resStride;
    float* out;        size_t outStride;
    int   cout;        int ngrp;           // ngrp = cout/16
    int   act;
};
struct ConvParams {
    Seg seg[3];
    int zStart[3];
    int nseg;
};

// ---------------- segmented pipelined 3x3 conv, 4px/thread vectorized ----------------
// tile: 32x32 px, 16 oc per CTA; thread: 1 row x 4 adjacent px x 16 oc.
// acc[j][i] = f32x2 over oc pair (2j,2j+1) at px0+i. x loads are LDS.128/LDS.64.
template<int CH, int DIL>
__global__ void __launch_bounds__(256, 2) conv3x3_seg(ConvParams p)
{
    constexpr int OCB = 16;
    constexpr int IW = convIW(DIL), IH = convIH(DIL);
    constexpr int PLANE = IH * RS;
    constexpr int NPF = cdiv_(PLANE, 256);
    constexpr int PPAD = NPF * 256;
    constexpr int WELEMS = CH * 9 * OCB;
    constexpr int NWF = cdiv_(WELEMS, 256);
    constexpr int WPAD = NWF * 256;
    constexpr int NXV = 4 + 2 * DIL;          // x values per (ci,ky): 6 (dil1) / 8 (dil2)

    extern __shared__ float smem[];

    const int tid = threadIdx.x;
    const int px0 = (tid & 7) * 4;            // 0,4,...,28
    const int py  = tid >> 3;                 // 0..31
    const int x0 = blockIdx.x * 32, y0 = blockIdx.y * 32;

    // segment select
    int z = blockIdx.z;
    int si = 0;
    if (p.nseg > 1 && z >= p.zStart[1]) si = 1;
    if (p.nseg > 2 && z >= p.zStart[2]) si = 2;
    z -= p.zStart[si];
    const Seg s = p.seg[si];

    const int img = z / s.ngrp;
    const int ocBase = (z % s.ngrp) * OCB;
    const int NCH = (s.cin + CH - 1) / CH;

    // ---- per-plane geometry offsets (row-padded layout) ----
    unsigned int offGeo[NPF];
    #pragma unroll
    for (int j = 0; j < NPF; ++j) {
        int idx = tid + j * 256;
        unsigned int o = 0x80000000u;
        if (idx < PLANE) {
            int ly = idx / RS, lx = idx % RS;
            int gy = y0 - DIL + ly, gx = x0 - DIL + lx;
            if (lx < IW && (unsigned)gy < (unsigned)IMH && (unsigned)gx < (unsigned)IMW)
                o = (unsigned int)(gy * IMW + gx);
        }
        offGeo[j] = o;
    }
    // ---- weight slot offsets ----
    unsigned int offW[NWF];
    int ciSlotW[NWF];
    #pragma unroll
    for (int j = 0; j < NWF; ++j) {
        int idx = tid + j * 256;
        if (idx < WELEMS) {
            int oc = idx & 15;
            int k  = (idx >> 4) % 9;
            int ci = (idx >> 4) / 9;
            offW[j] = (unsigned int)(((ocBase + oc) * s.cin + ci) * 9 + k);
            ciSlotW[j] = ci;
        } else { offW[j] = 0; ciSlotW[j] = 0x7FFFFFF; }
    }
    const unsigned int sBase = (unsigned int)__cvta_generic_to_shared(smem);

    unsigned long long acc[8][4];             // [oc pair][px]
    #pragma unroll
    for (int j = 0; j < 8; ++j)
        #pragma unroll
        for (int i = 0; i < 4; ++i) acc[j][i] = 0ULL;

    auto prefetch = [&](int cc, int b) {
        unsigned int sIn = sBase + (unsigned)(b * CH * PPAD) * 4;
        unsigned int sW  = sBase + (unsigned)((2 * CH * PPAD) + b * WPAD) * 4;
        const int chLim = s.cin - cc * CH;
        #pragma unroll
        for (int ci = 0; ci < CH; ++ci) {
            int g = cc * CH + ci;
            bool chOk = ci < chLim;
            const float* src = (g < s.cinA)
                ? s.in  + (size_t)img * s.inStride  + (size_t)g * HWSZ
                : s.in2 + (size_t)img * s.in2Stride + (size_t)(g - s.cinA) * HWSZ;
            #pragma unroll
            for (int j = 0; j < NPF; ++j) {
                unsigned int o = offGeo[j];
                bool ok = chOk && !(o & 0x80000000u);
                cpasync4(sIn + (unsigned)(ci * PPAD + tid + j * 256) * 4,
                         src + (o & 0x7FFFFFFFu), ok);
            }
        }
        const unsigned int wAdd = (unsigned int)(cc * CH) * 9u;
        #pragma unroll
        for (int j = 0; j < NWF; ++j) {
            bool ok = ciSlotW[j] < chLim;
            cpasync4(sW + (unsigned)(tid + j * 256) * 4,
                     s.W + (ok ? (offW[j] + wAdd) : 0u), ok);
        }
    };

    prefetch(0, 0);
    cpasync_commit();
    cpasync_wait0();
    __syncthreads();

    int buf = 0;
    #pragma unroll 1
    for (int cc = 0; cc < NCH; ++cc) {
        if (cc + 1 < NCH) prefetch(cc + 1, buf ^ 1);
        cpasync_commit();

        const float* sI = smem + buf * CH * PPAD;
        const float* sW = smem + 2 * CH * PPAD + buf * WPAD;
        #pragma unroll 1
        for (int ci = 0; ci < CH; ++ci) {
            const float* sIc = sI + ci * PPAD;
            const float* sWc = sW + ci * 9 * OCB;
            #pragma unroll
            for (int ky = 0; ky < 3; ++ky) {
                const float* rowp = sIc + (py + ky * DIL) * RS + px0;
                unsigned long long pk[NXV];
                {
                    float4 a = *reinterpret_cast<const float4*>(rowp);
                    pk[0] = packf2(a.x, a.x);
                    pk[1] = packf2(a.y, a.y);
                    pk[2] = packf2(a.z, a.z);
                    pk[3] = packf2(a.w, a.w);
                    if (DIL == 1) {
                        float2 b = *reinterpret_cast<const float2*>(rowp + 4);
                        pk[4] = packf2(b.x, b.x);
                        pk[5] = packf2(b.y, b.y);
                    } else {
                        float4 b = *reinterpret_cast<const float4*>(rowp + 4);
                        pk[4] = packf2(b.x, b.x);
                        pk[5] = packf2(b.y, b.y);
                        pk[NXV - 2] = packf2(b.z, b.z);
                        pk[NXV - 1] = packf2(b.w, b.w);
                    }
                }
                #pragma unroll
                for (int kx = 0; kx < 3; ++kx) {
                    const ulonglong2* wp =
                        reinterpret_cast<const ulonglong2*>(sWc + (ky * 3 + kx) * OCB);
                    #pragma unroll
                    for (int o4 = 0; o4 < 4; ++o4) {
                        ulonglong2 w2 = wp[o4];
                        #pragma unroll
                        for (int i = 0; i < 4; ++i) {
                            ffma2(acc[o4 * 2 + 0][i], pk[i + kx * DIL], w2.x);
                            ffma2(acc[o4 * 2 + 1][i], pk[i + kx * DIL], w2.y);
                        }
                    }
                }
            }
        }

        cpasync_wait0();
        __syncthreads();
        buf ^= 1;
    }

    const int ox = x0 + px0;
    const int oy = y0 + py;
    float* op = s.out + (size_t)img * s.outStride;
    #pragma unroll
    for (int j = 0; j < 8; ++j) {
        int oc0 = ocBase + 2 * j;
        float b0 = s.b[oc0];
        float b1 = s.b[oc0 + 1];
        float lo[4], hi[4];
        #pragma unroll
        for (int i = 0; i < 4; ++i) {
            unpackf2(acc[j][i], lo[i], hi[i]);
            lo[i] += b0;
            hi[i] += b1;
        }
        if (s.res != nullptr) {
            const float* rp = s.res + (size_t)img * s.resStride;
            float4 r0 = *reinterpret_cast<const float4*>(
                rp + (size_t)oc0 * HWSZ + oy * IMW + ox);
            float4 r1 = *reinterpret_cast<const float4*>(
                rp + (size_t)(oc0 + 1) * HWSZ + oy * IMW + ox);
            lo[0] += r0.x; lo[1] += r0.y; lo[2] += r0.z; lo[3] += r0.w;
            hi[0] += r1.x; hi[1] += r1.y; hi[2] += r1.z; hi[3] += r1.w;
        }
        if (s.act) {
            #pragma unroll
            for (int i = 0; i < 4; ++i) { lo[i] = lrelu(lo[i]); hi[i] = lrelu(hi[i]); }
        }
        *reinterpret_cast<float4*>(op + (size_t)oc0 * HWSZ + oy * IMW + ox)
            = make_float4(lo[0], lo[1], lo[2], lo[3]);
        *reinterpret_cast<float4*>(op + (size_t)(oc0 + 1) * HWSZ + oy * IMW + ox)
            = make_float4(hi[0], hi[1], hi[2], hi[3]);
    }
}

// ---------------- deformable attention ----------------
__global__ void deform_attn_kernel(const float* __restrict__ val,
                                   const float* __restrict__ off,
                                   const float* __restrict__ awl,
                                   float* __restrict__ out)
{
    int id = blockIdx.x * blockDim.x + threadIdx.x;
    if (id >= BB * 4 * HWSZ) return;
    int q = id % HWSZ;
    int head = (id / HWSZ) & 3;
    int b = id / (4 * HWSZ);
    int px = q & (IMW - 1), py = q >> 8;

    const float* awp = awl + ((size_t)b * 48 + head * 12) * HWSZ + q;
    float lg[12];
    float mx = -1e30f;
    #pragma unroll
    for (int i = 0; i < 12; ++i) { lg[i] = awp[(size_t)i * HWSZ]; mx = fmaxf(mx, lg[i]); }
    float s = 0.f;
    #pragma unroll
    for (int i = 0; i < 12; ++i) { lg[i] = expf(lg[i] - mx); s += lg[i]; }
    float inv = 1.f / s;

    float acc[8];
    #pragma unroll
    for (int e = 0; e < 8; ++e) acc[e] = 0.f;

    const float* offp = off + ((size_t)b * 96 + head * 24) * HWSZ + q;

    for (int l = 0; l < 3; ++l) {
        const float* vbase = val + (((size_t)b * 3 + l) * 32 + head * 8) * HWSZ;
        #pragma unroll
        for (int p = 0; p < 4; ++p) {
            int ch = (l * 4 + p) * 2;
            float sx = (float)px + offp[(size_t)ch * HWSZ];
            float sy = (float)py + offp[(size_t)(ch + 1) * HWSZ];
            float a = lg[l * 4 + p] * inv;

            float x0f = floorf(sx), y0f = floorf(sy);
            float lx = sx - x0f, ly = sy - y0f;
            int x0 = (int)x0f, y0 = (int)y0f;
            float w00 = (1.f - lx) * (1.f - ly);
            float w01 = lx * (1.f - ly);
            float w10 = (1.f - lx) * ly;
            float w11 = lx * ly;
            bool vx0 = (unsigned)x0       < (unsigned)IMW;
            bool vx1 = (unsigned)(x0 + 1) < (unsigned)IMW;
            bool vy0 = (unsigned)y0       < (unsigned)IMH;
            bool vy1 = (unsigned)(y0 + 1) < (unsigned)IMH;
            int cx0 = min(max(x0, 0), IMW - 1), cx1 = min(max(x0 + 1, 0), IMW - 1);
            int cy0 = min(max(y0, 0), IMH - 1), cy1 = min(max(y0 + 1, 0), IMH - 1);
            float c00 = (vx0 && vy0) ? a * w00 : 0.f;
            float c01 = (vx1 && vy0) ? a * w01 : 0.f;
            float c10 = (vx0 && vy1) ? a * w10 : 0.f;
            float c11 = (vx1 && vy1) ? a * w11 : 0.f;
            int i00 = cy0 * IMW + cx0, i01 = cy0 * IMW + cx1;
            int i10 = cy1 * IMW + cx0, i11 = cy1 * IMW + cx1;
            #pragma unroll
            for (int e = 0; e < 8; ++e) {
                const float* vp = vbase + (size_t)e * HWSZ;
                acc[e] += c00 * vp[i00] + c01 * vp[i01] + c10 * vp[i10] + c11 * vp[i11];
            }
        }
    }

    float* op = out + ((size_t)b * 32 + head * 8) * HWSZ + q;
    #pragma unroll
    for (int e = 0; e < 8; ++e) op[(size_t)e * HWSZ] = acc[e];
}

// ---------------- final 1x1 conv + lrelu ----------------
__global__ void conv1x1_lrelu_kernel(const float* __restrict__ in,
                                     const float* __restrict__ Wt,
                                     const float* __restrict__ bias,
                                     float* __restrict__ out)
{
    __shared__ float s_w[32][32];
    __shared__ float s_b[32];
    int tid = threadIdx.x;
    for (int idx = tid; idx < 32 * 32; idx += 256)
        s_w[idx >> 5][idx & 31] = Wt[idx];
    if (tid < 32) s_b[tid] = bias[tid];
    __syncthreads();

    int id = blockIdx.x * 256 + tid;
    if (id >= BB * HWSZ) return;
    int b = id / HWSZ, q = id % HWSZ;

    float x[32];
    #pragma unroll
    for (int ci = 0; ci < 32; ++ci)
        x[ci] = in[((size_t)b * 32 + ci) * HWSZ + q];

    #pragma unroll 4
    for (int oc = 0; oc < 32; ++oc) {
        float s = s_b[oc];
        #pragma unroll
        for (int ci = 0; ci < 32; ++ci)
            s += x[ci] * s_w[oc][ci];
        out[((size_t)b * 32 + oc) * HWSZ + q] = lrelu(s);
    }
}

// ---------------- host launcher ----------------
static void fillSeg(Seg& s, const float* in, size_t inStride, int cin,
                    const float* W, const float* b, float* out, size_t outStride,
                    int cout, int act,
                    const float* res = nullptr, size_t resStride = 0,
                    const float* in2 = nullptr, size_t in2Stride = 0, int cinA = -1)
{
    s.in = in; s.inStride = inStride;
    s.in2 = in2 ? in2 : in; s.in2Stride = in2 ? in2Stride : inStride;
    s.cinA = (cinA >= 0) ? cinA : cin;
    s.cin = cin; s.W = W; s.b = b;
    s.res = res; s.resStride = resStride;
    s.out = out; s.outStride = outStride;
    s.cout = cout; s.ngrp = cout / 16; s.act = act;
}

extern "C" void kernel_launch(void* const* d_in, const int* in_sizes, int n_in,
                              void* d_out, int out_size)
{
    const float* frame   = (const float*)d_in[0];
    const float* srcfr   = (const float*)d_in[1];
    const float* flow_f  = (const float*)d_in[2];
    const float* flow_b  = (const float*)d_in[3];
    const float* W_qk = (const float*)d_in[4];   const float* b_qk = (const float*)d_in[5];
    const float* W_v  = (const float*)d_in[6];   const float* b_v  = (const float*)d_in[7];
    const float* W_vp = (const float*)d_in[8];   const float* b_vp = (const float*)d_in[9];
    const float* W_off= (const float*)d_in[10];  const float* b_off= (const float*)d_in[11];
    const float* W_aw = (const float*)d_in[12];  const float* b_aw = (const float*)d_in[13];
    const float* W_out= (const float*)d_in[14];  const float* b_out= (const float*)d_in[15];
    const float* W_ffd= (const float*)d_in[16];  const float* b_ffd= (const float*)d_in[17];
    const float* W_ff1= (const float*)d_in[18];  const float* b_ff1= (const float*)d_in[19];
    const float* W_ff2= (const float*)d_in[20];  const float* b_ff2= (const float*)d_in[21];
    const float* W_fu = (const float*)d_in[22];  const float* b_fu = (const float*)d_in[23];

    float *qkin, *qureys, *value, *val, *off, *aw, *attn, *out1, *out2, *ff1, *out3;
    cudaGetSymbolAddress((void**)&qkin,   g_qkin);
    cudaGetSymbolAddress((void**)&qureys, g_qureys);
    cudaGetSymbolAddress((void**)&value,  g_value);
    cudaGetSymbolAddress((void**)&val,    g_val);
    cudaGetSymbolAddress((void**)&off,    g_off);
    cudaGetSymbolAddress((void**)&aw,     g_aw);
    cudaGetSymbolAddress((void**)&attn,   g_attn);
    cudaGetSymbolAddress((void**)&out1,   g_out1);
    cudaGetSymbolAddress((void**)&out2,   g_out2);
    cudaGetSymbolAddress((void**)&ff1,    g_ff1);
    cudaGetSymbolAddress((void**)&out3,   g_out3);

    constexpr int SM81 = convSmemBytes(8, 1);
    constexpr int SM82 = convSmemBytes(8, 2);

    cudaFuncSetAttribute(conv3x3_seg<8, 1>,
                         cudaFuncAttributeMaxDynamicSharedMemorySize, SM81);
    cudaFuncSetAttribute(conv3x3_seg<8, 2>,
                         cudaFuncAttributeMaxDynamicSharedMemorySize, SM82);

    const size_t H32 = (size_t)32 * HWSZ, H48 = (size_t)48 * HWSZ;
    const size_t H96 = (size_t)96 * HWSZ, H100 = (size_t)100 * HWSZ;

    // 1. qk_in
    build_qkin_kernel<<<(BB * HWSZ + 255) / 256, 256>>>(frame, flow_f, flow_b, qkin);

    // 2. merged: qureys = lrelu(conv(qkin,W_qk)) ; value = conv(frame,W_v)
    {
        ConvParams p{};
        fillSeg(p.seg[0], qkin, H100, 100, W_qk, b_qk, qureys, H96, 96, 1);
        fillSeg(p.seg[1], frame, H96,  96,  W_v,  b_v,  value,  H96, 96, 0);
        p.zStart[0] = 0; p.zStart[1] = BB * 6; p.nseg = 2;
        conv3x3_seg<8, 1><<<dim3(8, 8, BB * 12), 256, SM81>>>(p);
    }

    // 3. merged: val (6 imgs x 2 grp) ; off (BB x 6 grp) ; aw (BB x 3 grp)
    {
        ConvParams p{};
        fillSeg(p.seg[0], value,  H32, 32, W_vp,  b_vp,  val, H32, 32, 0);
        fillSeg(p.seg[1], qureys, H96, 96, W_off, b_off, off, H96, 96, 0);
        fillSeg(p.seg[2], qureys, H96, 96, W_aw,  b_aw,  aw,  H48, 48, 0);
        p.zStart[0] = 0; p.zStart[1] = 12; p.zStart[2] = 12 + BB * 6;
        p.nseg = 3;
        conv3x3_seg<8, 1><<<dim3(8, 8, 12 + BB * 6 + BB * 3), 256, SM81>>>(p);
    }

    // 4. deformable attention
    deform_attn_kernel<<<(BB * 4 * HWSZ + 255) / 256, 256>>>(val, off, aw, attn);

    // 5. out1 = conv(attn, W_out)
    {
        ConvParams p{};
        fillSeg(p.seg[0], attn, H32, 32, W_out, b_out, out1, H32, 32, 0);
        p.zStart[0] = 0; p.nseg = 1;
        conv3x3_seg<8, 1><<<dim3(8, 8, BB * 2), 256, SM81>>>(p);
    }

    // 6. out2 = conv(out1, W_ffd) + frame[:,1]
    {
        ConvParams p{};
        fillSeg(p.seg[0], out1, H32, 32, W_ffd, b_ffd, out2, H32, 32, 0,
                frame + H32, H96);
        p.zStart[0] = 0; p.nseg = 1;
        conv3x3_seg<8, 1><<<dim3(8, 8, BB * 2), 256, SM81>>>(p);
    }

    // 7. ff1 = lrelu(conv([out2, srcframe[:,1]], W_ff1, pad=2, dil=2))  (fused concat)
    {
        ConvParams p{};
        fillSeg(p.seg[0], out2, H32, 64, W_ff1, b_ff1, ff1, H32, 32, 1,
                nullptr, 0, srcfr + H32, H96, 32);
        p.zStart[0] = 0; p.nseg = 1;
        conv3x3_seg<8, 2><<<dim3(8, 8, BB * 2), 256, SM82>>>(p);
    }

    // 8. out3 = conv(ff1, W_ff2) + out2
    {
        ConvParams p{};
        fillSeg(p.seg[0], ff1, H32, 32, W_ff2, b_ff2, out3, H32, 32, 0,
                out2, H32);
        p.zStart[0] = 0; p.nseg = 1;
        conv3x3_seg<8, 1><<<dim3(8, 8, BB * 2), 256, SM81>>>(p);
    }

    // 9. out = lrelu(conv1x1(out3, W_fu))
    conv1x1_lrelu_kernel<<<(BB * HWSZ + 255) / 256, 256>>>(out3, W_fu, b_fu, (float*)d_out);
}